// round 1
// baseline (speedup 1.0000x reference)
#include <cuda_runtime.h>
#include <math.h>

#define HID 64
#define DN 128
#define DE 128
#define MAX_N 100000
#define MAX_E 1600000

// ---------------- device scratch (no allocations allowed) ----------------
__device__ float g_node_proj[MAX_N * HID];   // 25.6 MB
__device__ float g_h_new[MAX_N * HID];       // 25.6 MB
__device__ float g_Wt_edge[DE * HID];        // [k][j], k-major
__device__ float g_Wt_node[DN * HID];        // [k][j]
__device__ float g_Wbig[128 * 256];          // [k][j] combined GRU weights

// ---------------- zero h_new (must run every launch: graph replays) -------
__global__ void zero_hnew_kernel(int n4) {
    int i = blockIdx.x * blockDim.x + threadIdx.x;
    if (i < n4) reinterpret_cast<float4*>(g_h_new)[i] = make_float4(0.f, 0.f, 0.f, 0.f);
}

// ---------------- weight prep: transposes + GRU weight fusion ------------
// Wbig[k][j]:
//   k<64  (input = h_new dim k):  j<192 -> W_ih[j][k], else 0
//   k>=64 (input = hidden dim k-64): j<128 -> W_hh[j][k-64];
//                                    128<=j<192 -> 0; j>=192 -> W_hh[j-64][k-64]
// Output columns: [0:64)=r pre-act (i_r+h_r), [64:128)=z, [128:192)=gi_n, [192:256)=gh_n
__global__ void prep_kernel(const float* __restrict__ W_edge,
                            const float* __restrict__ W_node,
                            const float* __restrict__ W_ih,
                            const float* __restrict__ W_hh) {
    int idx = blockIdx.x * blockDim.x + threadIdx.x;
    if (idx < DE * HID) {
        int k = idx >> 6, j = idx & 63;
        g_Wt_edge[idx] = W_edge[j * DE + k];
        return;
    }
    int i2 = idx - DE * HID;
    if (i2 < DN * HID) {
        int k = i2 >> 6, j = i2 & 63;
        g_Wt_node[i2] = W_node[j * DN + k];
        return;
    }
    int i3 = i2 - DN * HID;
    if (i3 < 128 * 256) {
        int k = i3 >> 8, j = i3 & 255;
        float v = 0.f;
        if (k < 64) {
            if (j < 192) v = W_ih[j * 64 + k];
        } else {
            if (j < 128)      v = W_hh[j * 64 + (k - 64)];
            else if (j >= 192) v = W_hh[(j - 64) * 64 + (k - 64)];
        }
        g_Wbig[i3] = v;
    }
}

// ---------------- node_proj = node_feats @ W_node.T  [N,64] --------------
// Tile: 128 rows x 64 cols per block, 256 threads, thread tile 4x8, K=128.
__global__ void nodeproj_kernel(const float* __restrict__ nf, int N) {
    __shared__ float sm[16 * 132 + 16 * 64];
    float* As = sm;              // [16][132] transposed feats (k-major)
    float* Ws = sm + 16 * 132;   // [16][64]
    int t = threadIdx.x;
    int base = blockIdx.x * 128;
    int tj = t & 7;              // 8 col-groups of 8
    int te = t >> 3;             // 32 row-groups of 4
    float acc[4][8];
#pragma unroll
    for (int i = 0; i < 4; i++)
#pragma unroll
        for (int j = 0; j < 8; j++) acc[i][j] = 0.f;

    int le = t >> 1;             // 0..127 row for A load
    int lk8 = (t & 1) * 8;       // k-chunk base
    int wk = t >> 4, wj = (t & 15) * 4;

    for (int k0 = 0; k0 < 128; k0 += 16) {
        int row = base + le; if (row >= N) row = N - 1;
        const float* p = nf + (size_t)row * DN + k0 + lk8;
        float4 fa = *(const float4*)p;
        float4 fb = *(const float4*)(p + 4);
        As[(lk8 + 0) * 132 + le] = fa.x;
        As[(lk8 + 1) * 132 + le] = fa.y;
        As[(lk8 + 2) * 132 + le] = fa.z;
        As[(lk8 + 3) * 132 + le] = fa.w;
        As[(lk8 + 4) * 132 + le] = fb.x;
        As[(lk8 + 5) * 132 + le] = fb.y;
        As[(lk8 + 6) * 132 + le] = fb.z;
        As[(lk8 + 7) * 132 + le] = fb.w;
        *(float4*)(Ws + wk * 64 + wj) = *(const float4*)(g_Wt_node + (k0 + wk) * 64 + wj);
        __syncthreads();
#pragma unroll
        for (int k = 0; k < 16; k++) {
            float4 a  = *(float4*)(As + k * 132 + te * 4);
            float4 b0 = *(float4*)(Ws + k * 64 + tj * 8);
            float4 b1 = *(float4*)(Ws + k * 64 + tj * 8 + 4);
            float av[4] = {a.x, a.y, a.z, a.w};
            float bv[8] = {b0.x, b0.y, b0.z, b0.w, b1.x, b1.y, b1.z, b1.w};
#pragma unroll
            for (int i = 0; i < 4; i++)
#pragma unroll
                for (int j = 0; j < 8; j++) acc[i][j] = fmaf(av[i], bv[j], acc[i][j]);
        }
        __syncthreads();
    }
#pragma unroll
    for (int i = 0; i < 4; i++) {
        int row = base + te * 4 + i;
        if (row < N) {
            float4 v0 = make_float4(acc[i][0], acc[i][1], acc[i][2], acc[i][3]);
            float4 v1 = make_float4(acc[i][4], acc[i][5], acc[i][6], acc[i][7]);
            *(float4*)(g_node_proj + (size_t)row * 64 + tj * 8)     = v0;
            *(float4*)(g_node_proj + (size_t)row * 64 + tj * 8 + 4) = v1;
        }
    }
}

// ---------------- fused edge kernel --------------------------------------
// Per 128-edge block: GEMM (edge_feats @ W_edge.T) -> smem tile ->
// add gathered node_proj[src], softmax over H=64 (warp shfl), mul
// node_hidden[src], red.add into g_h_new[dst].
__global__ void edge_kernel(const float* __restrict__ ef,
                            const int* __restrict__ src,
                            const int* __restrict__ dst,
                            const float* __restrict__ hidden,
                            int E) {
    __shared__ float sm[128 * 68];      // 34.8 KB; overlays As/Ws then Ms
    float* As = sm;                     // [16][132]
    float* Ws = sm + 16 * 132;          // [16][64]
    int t = threadIdx.x;
    int base = blockIdx.x * 128;
    int tj = t & 7;
    int te = t >> 3;
    float acc[4][8];
#pragma unroll
    for (int i = 0; i < 4; i++)
#pragma unroll
        for (int j = 0; j < 8; j++) acc[i][j] = 0.f;

    int le = t >> 1;
    int lk8 = (t & 1) * 8;
    int wk = t >> 4, wj = (t & 15) * 4;

    for (int k0 = 0; k0 < 128; k0 += 16) {
        int row = base + le; if (row >= E) row = E - 1;
        const float* p = ef + (size_t)row * DE + k0 + lk8;
        float4 fa = *(const float4*)p;
        float4 fb = *(const float4*)(p + 4);
        As[(lk8 + 0) * 132 + le] = fa.x;
        As[(lk8 + 1) * 132 + le] = fa.y;
        As[(lk8 + 2) * 132 + le] = fa.z;
        As[(lk8 + 3) * 132 + le] = fa.w;
        As[(lk8 + 4) * 132 + le] = fb.x;
        As[(lk8 + 5) * 132 + le] = fb.y;
        As[(lk8 + 6) * 132 + le] = fb.z;
        As[(lk8 + 7) * 132 + le] = fb.w;
        *(float4*)(Ws + wk * 64 + wj) = *(const float4*)(g_Wt_edge + (k0 + wk) * 64 + wj);
        __syncthreads();
#pragma unroll
        for (int k = 0; k < 16; k++) {
            float4 a  = *(float4*)(As + k * 132 + te * 4);
            float4 b0 = *(float4*)(Ws + k * 64 + tj * 8);
            float4 b1 = *(float4*)(Ws + k * 64 + tj * 8 + 4);
            float av[4] = {a.x, a.y, a.z, a.w};
            float bv[8] = {b0.x, b0.y, b0.z, b0.w, b1.x, b1.y, b1.z, b1.w};
#pragma unroll
            for (int i = 0; i < 4; i++)
#pragma unroll
                for (int j = 0; j < 8; j++) acc[i][j] = fmaf(av[i], bv[j], acc[i][j]);
        }
        __syncthreads();
    }

    // stash the 128x64 edge_proj tile (overlays As/Ws; all compute done)
    float* Ms = sm;                     // [128][68]
#pragma unroll
    for (int i = 0; i < 4; i++) {
        float4 v0 = make_float4(acc[i][0], acc[i][1], acc[i][2], acc[i][3]);
        float4 v1 = make_float4(acc[i][4], acc[i][5], acc[i][6], acc[i][7]);
        *(float4*)(Ms + (size_t)(te * 4 + i) * 68 + tj * 8)     = v0;
        *(float4*)(Ms + (size_t)(te * 4 + i) * 68 + tj * 8 + 4) = v1;
    }
    __syncthreads();

    // phase 2: warp-per-edge softmax + gather + scatter (8 warps x 16 edges)
    int warp = t >> 5, lane = t & 31;
    for (int i = 0; i < 16; i++) {
        int e = warp * 16 + i;
        int ge = base + e;
        if (ge >= E) break;
        int s = __ldg(src + ge);
        int d = __ldg(dst + ge);
        float2 mv  = *(float2*)(Ms + (size_t)e * 68 + lane * 2);
        float2 npv = *(const float2*)(g_node_proj + (size_t)s * 64 + lane * 2);
        float v0 = mv.x + npv.x;
        float v1 = mv.y + npv.y;
        float mx = fmaxf(v0, v1);
#pragma unroll
        for (int o = 16; o > 0; o >>= 1) mx = fmaxf(mx, __shfl_xor_sync(0xffffffffu, mx, o));
        float e0 = __expf(v0 - mx);
        float e1 = __expf(v1 - mx);
        float ssum = e0 + e1;
#pragma unroll
        for (int o = 16; o > 0; o >>= 1) ssum += __shfl_xor_sync(0xffffffffu, ssum, o);
        float inv = 1.0f / ssum;
        float2 hv = *(const float2*)(hidden + (size_t)s * 64 + lane * 2);
        float o0 = hv.x * e0 * inv;
        float o1 = hv.y * e1 * inv;
        float* addr = g_h_new + (size_t)d * 64 + lane * 2;
        asm volatile("red.global.add.v2.f32 [%0], {%1, %2};"
                     :: "l"(addr), "f"(o0), "f"(o1) : "memory");
    }
}

// ---------------- GRU kernel ---------------------------------------------
// G = [h_new | hidden] (N x 128) @ Wbig (128 x 256), then gate math.
// Block: 32 nodes x 256 outputs, 256 threads, thread tile 4x8.
__global__ void gru_kernel(const float* __restrict__ hidden,
                           const float* __restrict__ b_ih,
                           const float* __restrict__ b_hh,
                           float* __restrict__ out, int N) {
    __shared__ float sm[32 * 260];      // 33.3 KB; Xs+Ws then Gs overlay
    float* Xs = sm;                     // [16][36]
    float* Ws = sm + 16 * 36;           // [16][256]
    int t = threadIdx.x;
    int base = blockIdx.x * 32;
    int tj = t & 31;                    // 32 col-groups of 8
    int tn = t >> 5;                    // 8 row-groups of 4
    float acc[4][8];
#pragma unroll
    for (int i = 0; i < 4; i++)
#pragma unroll
        for (int j = 0; j < 8; j++) acc[i][j] = 0.f;

    for (int k0 = 0; k0 < 128; k0 += 16) {
        if (t < 128) {
            int n = t >> 2;
            int kc = (t & 3) * 4;
            int k = k0 + kc;
            int row = base + n; if (row >= N) row = N - 1;
            const float* srcp = (k < 64) ? (g_h_new + (size_t)row * 64 + k)
                                         : (hidden + (size_t)row * 64 + (k - 64));
            float4 v = *(const float4*)srcp;
            Xs[(kc + 0) * 36 + n] = v.x;
            Xs[(kc + 1) * 36 + n] = v.y;
            Xs[(kc + 2) * 36 + n] = v.z;
            Xs[(kc + 3) * 36 + n] = v.w;
        }
#pragma unroll
        for (int r = 0; r < 4; r++) {
            int id = t + r * 256;               // float4 index into 16x256 tile
            int k = id >> 6;
            int jc = (id & 63) * 4;
            *(float4*)(Ws + k * 256 + jc) = *(const float4*)(g_Wbig + (size_t)(k0 + k) * 256 + jc);
        }
        __syncthreads();
#pragma unroll
        for (int k = 0; k < 16; k++) {
            float4 a  = *(float4*)(Xs + k * 36 + tn * 4);
            float4 b0 = *(float4*)(Ws + k * 256 + tj * 8);
            float4 b1 = *(float4*)(Ws + k * 256 + tj * 8 + 4);
            float av[4] = {a.x, a.y, a.z, a.w};
            float bv[8] = {b0.x, b0.y, b0.z, b0.w, b1.x, b1.y, b1.z, b1.w};
#pragma unroll
            for (int i = 0; i < 4; i++)
#pragma unroll
                for (int j = 0; j < 8; j++) acc[i][j] = fmaf(av[i], bv[j], acc[i][j]);
        }
        __syncthreads();
    }

    float* Gs = sm;                     // [32][260]
#pragma unroll
    for (int i = 0; i < 4; i++) {
        float4 v0 = make_float4(acc[i][0], acc[i][1], acc[i][2], acc[i][3]);
        float4 v1 = make_float4(acc[i][4], acc[i][5], acc[i][6], acc[i][7]);
        *(float4*)(Gs + (size_t)(tn * 4 + i) * 260 + tj * 8)     = v0;
        *(float4*)(Gs + (size_t)(tn * 4 + i) * 260 + tj * 8 + 4) = v1;
    }
    __syncthreads();

    int nn = t >> 3;                    // 0..31 local node
    int jb = (t & 7) * 8;               // 8 hidden dims per thread
    int row = base + nn;
    if (row < N) {
#pragma unroll
        for (int jj = 0; jj < 8; jj++) {
            int j = jb + jj;
            float gr = Gs[nn * 260 + j]        + b_ih[j]       + b_hh[j];
            float gz = Gs[nn * 260 + 64 + j]   + b_ih[64 + j]  + b_hh[64 + j];
            float gi = Gs[nn * 260 + 128 + j]  + b_ih[128 + j];
            float gh = Gs[nn * 260 + 192 + j]  + b_hh[128 + j];
            float r  = 1.0f / (1.0f + __expf(-gr));
            float z  = 1.0f / (1.0f + __expf(-gz));
            float ng = tanhf(fmaf(r, gh, gi));
            float h  = hidden[(size_t)row * 64 + j];
            out[(size_t)row * 64 + j] = fmaf(1.0f - z, ng, z * h);
        }
    }
}

// ---------------- launch --------------------------------------------------
extern "C" void kernel_launch(void* const* d_in, const int* in_sizes, int n_in,
                              void* d_out, int out_size) {
    const float* node_feats  = (const float*)d_in[0];
    const float* edge_feats  = (const float*)d_in[1];
    const float* node_hidden = (const float*)d_in[2];
    const int*   src         = (const int*)d_in[3];
    const int*   dst         = (const int*)d_in[4];
    const float* W_edge      = (const float*)d_in[5];
    const float* W_node      = (const float*)d_in[6];
    const float* W_ih        = (const float*)d_in[7];
    const float* W_hh        = (const float*)d_in[8];
    const float* b_ih        = (const float*)d_in[9];
    const float* b_hh        = (const float*)d_in[10];
    float* out = (float*)d_out;

    int E = in_sizes[3];                 // src element count
    int N = in_sizes[2] / HID;           // node_hidden = N * 64

    int n4 = N * (HID / 4);
    zero_hnew_kernel<<<(n4 + 255) / 256, 256>>>(n4);

    int prep_work = DE * HID + DN * HID + 128 * 256;
    prep_kernel<<<(prep_work + 255) / 256, 256>>>(W_edge, W_node, W_ih, W_hh);

    nodeproj_kernel<<<(N + 127) / 128, 256>>>(node_feats, N);

    edge_kernel<<<(E + 127) / 128, 256>>>(edge_feats, src, dst, node_hidden, E);

    gru_kernel<<<(N + 31) / 32, 256>>>(node_hidden, b_ih, b_hh, out, N);
}

// round 2
// speedup vs baseline: 4.2579x; 4.2579x over previous
#include <cuda_runtime.h>
#include <math.h>

#define HID 64
#define MAX_N 100000
#define MAX_E 1600000

// ---------------- device scratch (no allocations allowed) ----------------
__device__ float g_node_proj[MAX_N * HID];   // 25.6 MB
__device__ float g_h_new[MAX_N * HID];       // 25.6 MB
// bf16 weight images, pre-swizzled into the smem tile layout:
// tile row stride 256B (128 bf16), 16B chunks, chunk c of row r stored at
// byte r*256 + ((c ^ (r&7))*16).
__device__ uint4 g_Wb_edge[64 * 16];         // W_edge  [j][k] bf16
__device__ uint4 g_Wb_node[64 * 16];         // W_node  [j][k] bf16
__device__ uint4 g_Wb_big[256 * 16];         // fused GRU weights [j][k] bf16

// ---------------- helpers -------------------------------------------------
__device__ __forceinline__ unsigned f2bf2(float lo, float hi) {
    unsigned r;
    asm("cvt.rn.bf16x2.f32 %0, %1, %2;" : "=r"(r) : "f"(hi), "f"(lo));
    return r;
}

__device__ __forceinline__ int swz(int row, int chunk) {
    return row * 256 + ((chunk ^ (row & 7)) << 4);
}

__device__ __forceinline__ void mma16816(float c[4],
                                         unsigned a0, unsigned a1,
                                         unsigned a2, unsigned a3,
                                         unsigned b0, unsigned b1) {
    asm("mma.sync.aligned.m16n8k16.row.col.f32.bf16.bf16.f32 "
        "{%0,%1,%2,%3},{%4,%5,%6,%7},{%8,%9},{%0,%1,%2,%3};"
        : "+f"(c[0]), "+f"(c[1]), "+f"(c[2]), "+f"(c[3])
        : "r"(a0), "r"(a1), "r"(a2), "r"(a3), "r"(b0), "r"(b1));
}

// ---------------- zero h_new (every launch: graph replays) ----------------
__global__ void zero_hnew_kernel(int n4) {
    int i = blockIdx.x * blockDim.x + threadIdx.x;
    if (i < n4) reinterpret_cast<float4*>(g_h_new)[i] = make_float4(0.f, 0.f, 0.f, 0.f);
}

// ---------------- weight prep: bf16 convert + swizzle + GRU fusion --------
// Fused GRU weight [j][k], j in [0,256), k in [0,128):
//   cols of G: [0:64)=r pre-act, [64:128)=z, [128:192)=gi_n, [192:256)=gh_n
//   k<64  (h_new input):  j<192 -> W_ih[j][k],          j>=192 -> 0
//   k>=64 (hidden input): j<128 -> W_hh[j][k-64], 128<=j<192 -> 0,
//                         j>=192 -> W_hh[j-64][k-64]
__global__ void prep_kernel(const float* __restrict__ W_edge,
                            const float* __restrict__ W_node,
                            const float* __restrict__ W_ih,
                            const float* __restrict__ W_hh) {
    int idx = blockIdx.x * blockDim.x + threadIdx.x;  // one 16B chunk each
    float v[8];
    uint4* dst;
    if (idx < 1024) {
        int j = idx >> 4, c = idx & 15;
        const float* p = W_edge + j * 128 + c * 8;
#pragma unroll
        for (int i = 0; i < 8; i++) v[i] = p[i];
        dst = g_Wb_edge + (j * 16 + (c ^ (j & 7)));
    } else if (idx < 2048) {
        int i2 = idx - 1024;
        int j = i2 >> 4, c = i2 & 15;
        const float* p = W_node + j * 128 + c * 8;
#pragma unroll
        for (int i = 0; i < 8; i++) v[i] = p[i];
        dst = g_Wb_node + (j * 16 + (c ^ (j & 7)));
    } else if (idx < 6144) {
        int i3 = idx - 2048;
        int j = i3 >> 4, c = i3 & 15;
#pragma unroll
        for (int i = 0; i < 8; i++) {
            int k = c * 8 + i;
            float val = 0.f;
            if (k < 64) {
                if (j < 192) val = W_ih[j * 64 + k];
            } else {
                int kk = k - 64;
                if (j < 128)       val = W_hh[j * 64 + kk];
                else if (j >= 192) val = W_hh[(j - 64) * 64 + kk];
            }
            v[i] = val;
        }
        dst = g_Wb_big + (j * 16 + (c ^ (j & 7)));
    } else {
        return;
    }
    uint4 o;
    o.x = f2bf2(v[0], v[1]);
    o.y = f2bf2(v[2], v[3]);
    o.z = f2bf2(v[4], v[5]);
    o.w = f2bf2(v[6], v[7]);
    *dst = o;
}

// ---------------- node_proj = node_feats @ W_node.T  (bf16 mma) ----------
// Block: 128 rows x 64 cols, 256 threads (8 warps x M16), K=128.
__global__ void nodeproj_kernel(const float* __restrict__ nf, int N) {
    __shared__ __align__(16) char sm[49152];
    char* As = sm;                 // 128 x 256B bf16, swizzled
    char* Bs = sm + 32768;         // 64 x 256B bf16, swizzled
    float* Ms = (float*)sm;        // overlay [128][68] fp32 staging
    int t = threadIdx.x;
    int base = blockIdx.x * 128;

    // load + convert A
#pragma unroll
    for (int i = 0; i < 16; i++) {
        int idx = i * 256 + t;
        int row = idx >> 5, col4 = idx & 31;
        int r = base + row; if (r >= N) r = N - 1;
        float4 v = *(const float4*)(nf + (size_t)r * 128 + col4 * 4);
        unsigned p0 = f2bf2(v.x, v.y), p1 = f2bf2(v.z, v.w);
        *(uint2*)(As + swz(row, col4 >> 1) + (col4 & 1) * 8) = make_uint2(p0, p1);
    }
    // copy B (pre-swizzled)
#pragma unroll
    for (int i = 0; i < 4; i++) ((uint4*)Bs)[i * 256 + t] = g_Wb_node[i * 256 + t];
    __syncthreads();

    int lane = t & 31, w = t >> 5;
    int mr = w * 16;
    int qr = lane >> 2, qc = (lane & 3) * 4;
    float acc[8][4];
#pragma unroll
    for (int n = 0; n < 8; n++)
#pragma unroll
        for (int q = 0; q < 4; q++) acc[n][q] = 0.f;

#pragma unroll
    for (int k0 = 0; k0 < 128; k0 += 16) {
        int c0 = k0 >> 3, c1 = c0 + 1;
        unsigned a0 = *(unsigned*)(As + swz(mr + qr, c0) + qc);
        unsigned a1 = *(unsigned*)(As + swz(mr + qr + 8, c0) + qc);
        unsigned a2 = *(unsigned*)(As + swz(mr + qr, c1) + qc);
        unsigned a3 = *(unsigned*)(As + swz(mr + qr + 8, c1) + qc);
#pragma unroll
        for (int nt = 0; nt < 8; nt++) {
            unsigned b0 = *(unsigned*)(Bs + swz(nt * 8 + qr, c0) + qc);
            unsigned b1 = *(unsigned*)(Bs + swz(nt * 8 + qr, c1) + qc);
            mma16816(acc[nt], a0, a1, a2, a3, b0, b1);
        }
    }
    __syncthreads();
    // stage to Ms then coalesced store
#pragma unroll
    for (int nt = 0; nt < 8; nt++) {
        int col = nt * 8 + (lane & 3) * 2;
        *(float2*)(Ms + (mr + qr) * 68 + col)     = make_float2(acc[nt][0], acc[nt][1]);
        *(float2*)(Ms + (mr + qr + 8) * 68 + col) = make_float2(acc[nt][2], acc[nt][3]);
    }
    __syncthreads();
#pragma unroll
    for (int i = 0; i < 8; i++) {
        int idx = i * 256 + t;
        int row = idx >> 4, c4 = idx & 15;
        int r = base + row;
        if (r < N)
            *(float4*)(g_node_proj + (size_t)r * 64 + c4 * 4) = *(float4*)(Ms + row * 68 + c4 * 4);
    }
}

// ---------------- fused edge kernel (bf16 mma GEMM + softmax + scatter) ---
__global__ void edge_kernel(const float* __restrict__ ef,
                            const int* __restrict__ src,
                            const int* __restrict__ dst,
                            const float* __restrict__ hidden,
                            int E) {
    __shared__ __align__(16) char sm[49152];
    char* As = sm;                 // 128 x 256B bf16
    char* Bs = sm + 32768;         // 64 x 256B bf16
    float* Ms = (float*)sm;        // overlay [128][68] fp32
    int t = threadIdx.x;
    int base = blockIdx.x * 128;

#pragma unroll
    for (int i = 0; i < 16; i++) {
        int idx = i * 256 + t;
        int row = idx >> 5, col4 = idx & 31;
        int r = base + row; if (r >= E) r = E - 1;
        float4 v = *(const float4*)(ef + (size_t)r * 128 + col4 * 4);
        unsigned p0 = f2bf2(v.x, v.y), p1 = f2bf2(v.z, v.w);
        *(uint2*)(As + swz(row, col4 >> 1) + (col4 & 1) * 8) = make_uint2(p0, p1);
    }
#pragma unroll
    for (int i = 0; i < 4; i++) ((uint4*)Bs)[i * 256 + t] = g_Wb_edge[i * 256 + t];
    __syncthreads();

    int lane = t & 31, w = t >> 5;
    int mr = w * 16;
    int qr = lane >> 2, qc = (lane & 3) * 4;
    float acc[8][4];
#pragma unroll
    for (int n = 0; n < 8; n++)
#pragma unroll
        for (int q = 0; q < 4; q++) acc[n][q] = 0.f;

#pragma unroll
    for (int k0 = 0; k0 < 128; k0 += 16) {
        int c0 = k0 >> 3, c1 = c0 + 1;
        unsigned a0 = *(unsigned*)(As + swz(mr + qr, c0) + qc);
        unsigned a1 = *(unsigned*)(As + swz(mr + qr + 8, c0) + qc);
        unsigned a2 = *(unsigned*)(As + swz(mr + qr, c1) + qc);
        unsigned a3 = *(unsigned*)(As + swz(mr + qr + 8, c1) + qc);
#pragma unroll
        for (int nt = 0; nt < 8; nt++) {
            unsigned b0 = *(unsigned*)(Bs + swz(nt * 8 + qr, c0) + qc);
            unsigned b1 = *(unsigned*)(Bs + swz(nt * 8 + qr, c1) + qc);
            mma16816(acc[nt], a0, a1, a2, a3, b0, b1);
        }
    }
    __syncthreads();   // done reading As/Bs; overlay Ms
#pragma unroll
    for (int nt = 0; nt < 8; nt++) {
        int col = nt * 8 + (lane & 3) * 2;
        *(float2*)(Ms + (mr + qr) * 68 + col)     = make_float2(acc[nt][0], acc[nt][1]);
        *(float2*)(Ms + (mr + qr + 8) * 68 + col) = make_float2(acc[nt][2], acc[nt][3]);
    }
    __syncthreads();

    // phase 2: warp-per-edge softmax + gather + scatter (8 warps x 16 edges)
    for (int i = 0; i < 16; i++) {
        int e = w * 16 + i;
        int ge = base + e;
        if (ge >= E) break;
        int s = __ldg(src + ge);
        int d = __ldg(dst + ge);
        float2 mv  = *(float2*)(Ms + (size_t)e * 68 + lane * 2);
        float2 npv = *(const float2*)(g_node_proj + (size_t)s * 64 + lane * 2);
        float v0 = mv.x + npv.x;
        float v1 = mv.y + npv.y;
        float mx = fmaxf(v0, v1);
#pragma unroll
        for (int o = 16; o > 0; o >>= 1) mx = fmaxf(mx, __shfl_xor_sync(0xffffffffu, mx, o));
        float e0 = __expf(v0 - mx);
        float e1 = __expf(v1 - mx);
        float ssum = e0 + e1;
#pragma unroll
        for (int o = 16; o > 0; o >>= 1) ssum += __shfl_xor_sync(0xffffffffu, ssum, o);
        float inv = 1.0f / ssum;
        float2 hv = *(const float2*)(hidden + (size_t)s * 64 + lane * 2);
        float o0 = hv.x * e0 * inv;
        float o1 = hv.y * e1 * inv;
        float* addr = g_h_new + (size_t)d * 64 + lane * 2;
        asm volatile("red.global.add.v2.f32 [%0], {%1, %2};"
                     :: "l"(addr), "f"(o0), "f"(o1) : "memory");
    }
}

// ---------------- GRU kernel (bf16 mma, fused 256-wide gate GEMM) ---------
// Block: 64 nodes x 256 cols, 256 threads. Warp w: mrows (w&3)*16, ncols (w>>2)*128.
// Dynamic smem: A 16KB + B 64KB, overlay Gs [64][260] fp32 (66.6KB).
__global__ void gru_kernel(const float* __restrict__ hidden,
                           const float* __restrict__ b_ih,
                           const float* __restrict__ b_hh,
                           float* __restrict__ out, int N) {
    extern __shared__ __align__(16) char dsm[];
    char* As = dsm;                // 64 x 256B
    char* Bs = dsm + 16384;        // 256 x 256B
    float* Gs = (float*)dsm;       // overlay [64][260]
    int t = threadIdx.x;
    int base = blockIdx.x * 64;

    // A = [h_new | hidden] rows, converted to bf16
#pragma unroll
    for (int i = 0; i < 8; i++) {
        int idx = i * 256 + t;
        int row = idx >> 5, col4 = idx & 31;
        int r = base + row; if (r >= N) r = N - 1;
        const float* p = (col4 < 16) ? (g_h_new + (size_t)r * 64 + col4 * 4)
                                     : (hidden  + (size_t)r * 64 + (col4 - 16) * 4);
        float4 v = *(const float4*)p;
        unsigned p0 = f2bf2(v.x, v.y), p1 = f2bf2(v.z, v.w);
        *(uint2*)(As + swz(row, col4 >> 1) + (col4 & 1) * 8) = make_uint2(p0, p1);
    }
#pragma unroll
    for (int i = 0; i < 16; i++) ((uint4*)Bs)[i * 256 + t] = g_Wb_big[i * 256 + t];
    __syncthreads();

    int lane = t & 31, w = t >> 5;
    int mr = (w & 3) * 16;
    int ncb = (w >> 2) * 128;
    int qr = lane >> 2, qc = (lane & 3) * 4;
    float acc[16][4];
#pragma unroll
    for (int n = 0; n < 16; n++)
#pragma unroll
        for (int q = 0; q < 4; q++) acc[n][q] = 0.f;

#pragma unroll
    for (int k0 = 0; k0 < 128; k0 += 16) {
        int c0 = k0 >> 3, c1 = c0 + 1;
        unsigned a0 = *(unsigned*)(As + swz(mr + qr, c0) + qc);
        unsigned a1 = *(unsigned*)(As + swz(mr + qr + 8, c0) + qc);
        unsigned a2 = *(unsigned*)(As + swz(mr + qr, c1) + qc);
        unsigned a3 = *(unsigned*)(As + swz(mr + qr + 8, c1) + qc);
#pragma unroll
        for (int nt = 0; nt < 16; nt++) {
            unsigned b0 = *(unsigned*)(Bs + swz(ncb + nt * 8 + qr, c0) + qc);
            unsigned b1 = *(unsigned*)(Bs + swz(ncb + nt * 8 + qr, c1) + qc);
            mma16816(acc[nt], a0, a1, a2, a3, b0, b1);
        }
    }
    __syncthreads();   // done with As/Bs; overlay Gs
#pragma unroll
    for (int nt = 0; nt < 16; nt++) {
        int col = ncb + nt * 8 + (lane & 3) * 2;
        *(float2*)(Gs + (mr + qr) * 260 + col)     = make_float2(acc[nt][0], acc[nt][1]);
        *(float2*)(Gs + (mr + qr + 8) * 260 + col) = make_float2(acc[nt][2], acc[nt][3]);
    }
    __syncthreads();

    int row = t >> 2;                 // 0..63
    int jb = (t & 3) * 16;
    int gr_ = base + row;
    if (gr_ < N) {
#pragma unroll
        for (int jj = 0; jj < 16; jj++) {
            int j = jb + jj;
            float pr = Gs[row * 260 + j]       + b_ih[j]        + b_hh[j];
            float pz = Gs[row * 260 + 64 + j]  + b_ih[64 + j]   + b_hh[64 + j];
            float pi = Gs[row * 260 + 128 + j] + b_ih[128 + j];
            float ph = Gs[row * 260 + 192 + j] + b_hh[128 + j];
            float r = 1.0f / (1.0f + __expf(-pr));
            float z = 1.0f / (1.0f + __expf(-pz));
            float ng = tanhf(fmaf(r, ph, pi));
            float h = hidden[(size_t)gr_ * 64 + j];
            out[(size_t)gr_ * 64 + j] = fmaf(1.0f - z, ng, z * h);
        }
    }
}

// ---------------- launch --------------------------------------------------
extern "C" void kernel_launch(void* const* d_in, const int* in_sizes, int n_in,
                              void* d_out, int out_size) {
    const float* node_feats  = (const float*)d_in[0];
    const float* edge_feats  = (const float*)d_in[1];
    const float* node_hidden = (const float*)d_in[2];
    const int*   src         = (const int*)d_in[3];
    const int*   dst         = (const int*)d_in[4];
    const float* W_edge      = (const float*)d_in[5];
    const float* W_node      = (const float*)d_in[6];
    const float* W_ih        = (const float*)d_in[7];
    const float* W_hh        = (const float*)d_in[8];
    const float* b_ih        = (const float*)d_in[9];
    const float* b_hh        = (const float*)d_in[10];
    float* out = (float*)d_out;

    int E = in_sizes[3];
    int N = in_sizes[2] / HID;

    int n4 = N * (HID / 4);
    zero_hnew_kernel<<<(n4 + 255) / 256, 256>>>(n4);

    prep_kernel<<<24, 256>>>(W_edge, W_node, W_ih, W_hh);

    nodeproj_kernel<<<(N + 127) / 128, 256>>>(node_feats, N);

    edge_kernel<<<(E + 127) / 128, 256>>>(edge_feats, src, dst, node_hidden, E);

    static const int GRU_SMEM = 16384 + 65536;  // 80 KB dynamic
    cudaFuncSetAttribute(gru_kernel, cudaFuncAttributeMaxDynamicSharedMemorySize, GRU_SMEM);
    gru_kernel<<<(N + 63) / 64, 256, GRU_SMEM>>>(node_hidden, b_ih, b_hh, out, N);
}

// round 4
// speedup vs baseline: 5.4133x; 1.2713x over previous
#include <cuda_runtime.h>
#include <math.h>

#define HID 64
#define MAX_N 100000
#define MAX_E 1600000

// ---------------- device scratch (no allocations allowed) ----------------
// packed per-node gather row: [0:64)=node_proj, [64:128)=node_hidden (51.2MB)
__device__ float g_packed[MAX_N * 128];
__device__ float g_h_new[MAX_N * HID];       // 25.6 MB
// bf16 weight images, pre-swizzled into the smem tile layout:
// tile row stride 256B (128 bf16), 16B chunks, chunk c of row r stored at
// byte r*256 + ((c ^ (r&7))*16).
__device__ uint4 g_Wb_edge[64 * 16];         // W_edge  [j][k] bf16
__device__ uint4 g_Wb_node[64 * 16];         // W_node  [j][k] bf16
__device__ uint4 g_Wb_big[256 * 16];         // fused GRU weights [j][k] bf16

// ---------------- helpers -------------------------------------------------
__device__ __forceinline__ unsigned f2bf2(float lo, float hi) {
    unsigned r;
    asm("cvt.rn.bf16x2.f32 %0, %1, %2;" : "=r"(r) : "f"(hi), "f"(lo));
    return r;
}

__device__ __forceinline__ int swz(int row, int chunk) {
    return row * 256 + ((chunk ^ (row & 7)) << 4);
}

__device__ __forceinline__ void mma16816(float c[4],
                                         unsigned a0, unsigned a1,
                                         unsigned a2, unsigned a3,
                                         unsigned b0, unsigned b1) {
    asm("mma.sync.aligned.m16n8k16.row.col.f32.bf16.bf16.f32 "
        "{%0,%1,%2,%3},{%4,%5,%6,%7},{%8,%9},{%0,%1,%2,%3};"
        : "+f"(c[0]), "+f"(c[1]), "+f"(c[2]), "+f"(c[3])
        : "r"(a0), "r"(a1), "r"(a2), "r"(a3), "r"(b0), "r"(b1));
}

// ---------------- init: zero h_new + copy hidden into packed table --------
__global__ void init_kernel(const float* __restrict__ hidden, int N) {
    int i = blockIdx.x * blockDim.x + threadIdx.x;   // one float4 each
    int n16 = N * 16;
    if (i < n16) {
        reinterpret_cast<float4*>(g_h_new)[i] = make_float4(0.f, 0.f, 0.f, 0.f);
        int row = i >> 4, c = i & 15;
        *(float4*)(g_packed + (size_t)row * 128 + 64 + c * 4) =
            *(const float4*)(hidden + (size_t)row * 64 + c * 4);
    }
}

// ---------------- weight prep: bf16 convert + swizzle + GRU fusion --------
// Fused GRU weight [j][k], j in [0,256), k in [0,128):
//   cols of G: [0:64)=r pre-act, [64:128)=z, [128:192)=gi_n, [192:256)=gh_n
__global__ void prep_kernel(const float* __restrict__ W_edge,
                            const float* __restrict__ W_node,
                            const float* __restrict__ W_ih,
                            const float* __restrict__ W_hh) {
    int idx = blockIdx.x * blockDim.x + threadIdx.x;  // one 16B chunk each
    float v[8];
    uint4* dst;
    if (idx < 1024) {
        int j = idx >> 4, c = idx & 15;
        const float* p = W_edge + j * 128 + c * 8;
#pragma unroll
        for (int i = 0; i < 8; i++) v[i] = p[i];
        dst = g_Wb_edge + (j * 16 + (c ^ (j & 7)));
    } else if (idx < 2048) {
        int i2 = idx - 1024;
        int j = i2 >> 4, c = i2 & 15;
        const float* p = W_node + j * 128 + c * 8;
#pragma unroll
        for (int i = 0; i < 8; i++) v[i] = p[i];
        dst = g_Wb_node + (j * 16 + (c ^ (j & 7)));
    } else if (idx < 6144) {
        int i3 = idx - 2048;
        int j = i3 >> 4, c = i3 & 15;
#pragma unroll
        for (int i = 0; i < 8; i++) {
            int k = c * 8 + i;
            float val = 0.f;
            if (k < 64) {
                if (j < 192) val = W_ih[j * 64 + k];
            } else {
                int kk = k - 64;
                if (j < 128)       val = W_hh[j * 64 + kk];
                else if (j >= 192) val = W_hh[(j - 64) * 64 + kk];
            }
            v[i] = val;
        }
        dst = g_Wb_big + (j * 16 + (c ^ (j & 7)));
    } else {
        return;
    }
    uint4 o;
    o.x = f2bf2(v[0], v[1]);
    o.y = f2bf2(v[2], v[3]);
    o.z = f2bf2(v[4], v[5]);
    o.w = f2bf2(v[6], v[7]);
    *dst = o;
}

// ---------------- node_proj = node_feats @ W_node.T -> g_packed[:,0:64] ---
__global__ void nodeproj_kernel(const float* __restrict__ nf, int N) {
    __shared__ __align__(16) char sm[49152];
    char* As = sm;                 // 128 x 256B bf16, swizzled
    char* Bs = sm + 32768;         // 64 x 256B bf16, swizzled
    float* Ms = (float*)sm;        // overlay [128][68] fp32 staging
    int t = threadIdx.x;
    int base = blockIdx.x * 128;

#pragma unroll
    for (int i = 0; i < 16; i++) {
        int idx = i * 256 + t;
        int row = idx >> 5, col4 = idx & 31;
        int r = base + row; if (r >= N) r = N - 1;
        float4 v = *(const float4*)(nf + (size_t)r * 128 + col4 * 4);
        unsigned p0 = f2bf2(v.x, v.y), p1 = f2bf2(v.z, v.w);
        *(uint2*)(As + swz(row, col4 >> 1) + (col4 & 1) * 8) = make_uint2(p0, p1);
    }
#pragma unroll
    for (int i = 0; i < 4; i++) ((uint4*)Bs)[i * 256 + t] = g_Wb_node[i * 256 + t];
    __syncthreads();

    int lane = t & 31, w = t >> 5;
    int mr = w * 16;
    int qr = lane >> 2, qc = (lane & 3) * 4;
    float acc[8][4];
#pragma unroll
    for (int n = 0; n < 8; n++)
#pragma unroll
        for (int q = 0; q < 4; q++) acc[n][q] = 0.f;

#pragma unroll
    for (int k0 = 0; k0 < 128; k0 += 16) {
        int c0 = k0 >> 3, c1 = c0 + 1;
        unsigned a0 = *(unsigned*)(As + swz(mr + qr, c0) + qc);
        unsigned a1 = *(unsigned*)(As + swz(mr + qr + 8, c0) + qc);
        unsigned a2 = *(unsigned*)(As + swz(mr + qr, c1) + qc);
        unsigned a3 = *(unsigned*)(As + swz(mr + qr + 8, c1) + qc);
#pragma unroll
        for (int nt = 0; nt < 8; nt++) {
            unsigned b0 = *(unsigned*)(Bs + swz(nt * 8 + qr, c0) + qc);
            unsigned b1 = *(unsigned*)(Bs + swz(nt * 8 + qr, c1) + qc);
            mma16816(acc[nt], a0, a1, a2, a3, b0, b1);
        }
    }
    __syncthreads();
#pragma unroll
    for (int nt = 0; nt < 8; nt++) {
        int col = nt * 8 + (lane & 3) * 2;
        *(float2*)(Ms + (mr + qr) * 68 + col)     = make_float2(acc[nt][0], acc[nt][1]);
        *(float2*)(Ms + (mr + qr + 8) * 68 + col) = make_float2(acc[nt][2], acc[nt][3]);
    }
    __syncthreads();
#pragma unroll
    for (int i = 0; i < 8; i++) {
        int idx = i * 256 + t;
        int row = idx >> 4, c4 = idx & 15;
        int r = base + row;
        if (r < N)
            *(float4*)(g_packed + (size_t)r * 128 + c4 * 4) = *(float4*)(Ms + row * 68 + c4 * 4);
    }
}

// ---------------- fused edge kernel (bf16 mma GEMM + softmax + scatter) ---
__global__ void edge_kernel(const float* __restrict__ ef,
                            const int* __restrict__ src,
                            const int* __restrict__ dst,
                            int E) {
    __shared__ __align__(16) char sm[49152];
    char* As = sm;                 // 128 x 256B bf16
    char* Bs = sm + 32768;         // 64 x 256B bf16
    float* Ms = (float*)sm;        // overlay [128][68] fp32
    int t = threadIdx.x;
    int base = blockIdx.x * 128;

#pragma unroll
    for (int i = 0; i < 16; i++) {
        int idx = i * 256 + t;
        int row = idx >> 5, col4 = idx & 31;
        int r = base + row; if (r >= E) r = E - 1;
        float4 v = *(const float4*)(ef + (size_t)r * 128 + col4 * 4);
        unsigned p0 = f2bf2(v.x, v.y), p1 = f2bf2(v.z, v.w);
        *(uint2*)(As + swz(row, col4 >> 1) + (col4 & 1) * 8) = make_uint2(p0, p1);
    }
#pragma unroll
    for (int i = 0; i < 4; i++) ((uint4*)Bs)[i * 256 + t] = g_Wb_edge[i * 256 + t];
    __syncthreads();

    int lane = t & 31, w = t >> 5;
    int mr = w * 16;
    int qr = lane >> 2, qc = (lane & 3) * 4;
    float acc[8][4];
#pragma unroll
    for (int n = 0; n < 8; n++)
#pragma unroll
        for (int q = 0; q < 4; q++) acc[n][q] = 0.f;

#pragma unroll
    for (int k0 = 0; k0 < 128; k0 += 16) {
        int c0 = k0 >> 3, c1 = c0 + 1;
        unsigned a0 = *(unsigned*)(As + swz(mr + qr, c0) + qc);
        unsigned a1 = *(unsigned*)(As + swz(mr + qr + 8, c0) + qc);
        unsigned a2 = *(unsigned*)(As + swz(mr + qr, c1) + qc);
        unsigned a3 = *(unsigned*)(As + swz(mr + qr + 8, c1) + qc);
#pragma unroll
        for (int nt = 0; nt < 8; nt++) {
            unsigned b0 = *(unsigned*)(Bs + swz(nt * 8 + qr, c0) + qc);
            unsigned b1 = *(unsigned*)(Bs + swz(nt * 8 + qr, c1) + qc);
            mma16816(acc[nt], a0, a1, a2, a3, b0, b1);
        }
    }
    __syncthreads();   // done reading As/Bs; overlay Ms
#pragma unroll
    for (int nt = 0; nt < 8; nt++) {
        int col = nt * 8 + (lane & 3) * 2;
        *(float2*)(Ms + (mr + qr) * 68 + col)     = make_float2(acc[nt][0], acc[nt][1]);
        *(float2*)(Ms + (mr + qr + 8) * 68 + col) = make_float2(acc[nt][2], acc[nt][3]);
    }
    __syncthreads();

    // ---- phase 2: 2 edges per warp iteration ----
    // lanes 0-15 compute softmax for edge a, lanes 16-31 for edge b (4 vals each).
    int half = lane >> 4;          // 0 or 1
    int hl = lane & 15;            // 0..15
    if (base + 128 <= E) {
#pragma unroll 4
        for (int i = 0; i < 8; i++) {
            int ea = w * 16 + 2 * i;
            int gea = base + ea;
            int sa = __ldg(src + gea), sb = __ldg(src + gea + 1);
            int da = __ldg(dst + gea), db = __ldg(dst + gea + 1);
            // full packed rows: lanes 0-15 -> proj part, 16-31 -> hidden part
            float4 ga = __ldg((const float4*)(g_packed + (size_t)sa * 128) + lane);
            float4 gb = __ldg((const float4*)(g_packed + (size_t)sb * 128) + lane);
            // swap halves of gb: half0 gets hidden_b, half1 gets proj_b
            float4 gbx;
            gbx.x = __shfl_xor_sync(0xffffffffu, gb.x, 16);
            gbx.y = __shfl_xor_sync(0xffffffffu, gb.y, 16);
            gbx.z = __shfl_xor_sync(0xffffffffu, gb.z, 16);
            gbx.w = __shfl_xor_sync(0xffffffffu, gb.w, 16);
            float4 proj = half ? gbx : ga;   // proj of MY edge, cols hl*4..
            float4 hidv = half ? ga : gbx;   // hidden of the OTHER edge
            float4 msg = *(float4*)(Ms + (size_t)(ea + half) * 68 + hl * 4);
            float v0 = proj.x + msg.x, v1 = proj.y + msg.y;
            float v2 = proj.z + msg.z, v3 = proj.w + msg.w;
            float mx = fmaxf(fmaxf(v0, v1), fmaxf(v2, v3));
#pragma unroll
            for (int o = 8; o > 0; o >>= 1)
                mx = fmaxf(mx, __shfl_xor_sync(0xffffffffu, mx, o));
            float e0 = __expf(v0 - mx), e1 = __expf(v1 - mx);
            float e2 = __expf(v2 - mx), e3 = __expf(v3 - mx);
            float ssum = (e0 + e1) + (e2 + e3);
#pragma unroll
            for (int o = 8; o > 0; o >>= 1)
                ssum += __shfl_xor_sync(0xffffffffu, ssum, o);
            float inv = 1.0f / ssum;
            float a0 = e0 * inv, a1 = e1 * inv, a2 = e2 * inv, a3 = e3 * inv;
            // swap alphas across halves: now each lane has alpha of the OTHER edge
            float b0 = __shfl_xor_sync(0xffffffffu, a0, 16);
            float b1 = __shfl_xor_sync(0xffffffffu, a1, 16);
            float b2 = __shfl_xor_sync(0xffffffffu, a2, 16);
            float b3 = __shfl_xor_sync(0xffffffffu, a3, 16);
            float m0 = hidv.x * b0, m1 = hidv.y * b1;
            float m2 = hidv.z * b2, m3 = hidv.w * b3;
            float* addr = g_h_new + (size_t)(half ? da : db) * 64 + hl * 4;
            asm volatile("red.global.add.v4.f32 [%0], {%1, %2, %3, %4};"
                         :: "l"(addr), "f"(m0), "f"(m1), "f"(m2), "f"(m3) : "memory");
        }
    } else {
        // tail tile: per-edge path (32 lanes x float2)
        for (int i = 0; i < 16; i++) {
            int e = w * 16 + i;
            int ge = base + e;
            if (ge >= E) break;
            int s = __ldg(src + ge);
            int d = __ldg(dst + ge);
            float2 mv  = *(float2*)(Ms + (size_t)e * 68 + lane * 2);
            float2 npv = *(const float2*)(g_packed + (size_t)s * 128 + lane * 2);
            float v0 = mv.x + npv.x;
            float v1 = mv.y + npv.y;
            float mx = fmaxf(v0, v1);
#pragma unroll
            for (int o = 16; o > 0; o >>= 1) mx = fmaxf(mx, __shfl_xor_sync(0xffffffffu, mx, o));
            float e0 = __expf(v0 - mx);
            float e1 = __expf(v1 - mx);
            float ssum = e0 + e1;
#pragma unroll
            for (int o = 16; o > 0; o >>= 1) ssum += __shfl_xor_sync(0xffffffffu, ssum, o);
            float inv = 1.0f / ssum;
            float2 hv = *(const float2*)(g_packed + (size_t)s * 128 + 64 + lane * 2);
            float o0 = hv.x * e0 * inv;
            float o1 = hv.y * e1 * inv;
            float* addr = g_h_new + (size_t)d * 64 + lane * 2;
            asm volatile("red.global.add.v2.f32 [%0], {%1, %2};"
                         :: "l"(addr), "f"(o0), "f"(o1) : "memory");
        }
    }
}

// ---------------- GRU kernel (bf16 mma, fused 256-wide gate GEMM) ---------
__global__ void gru_kernel(const float* __restrict__ hidden,
                           const float* __restrict__ b_ih,
                           const float* __restrict__ b_hh,
                           float* __restrict__ out, int N) {
    extern __shared__ __align__(16) char dsm[];
    char* As = dsm;                // 64 x 256B
    char* Bs = dsm + 16384;        // 256 x 256B
    float* Gs = (float*)dsm;       // overlay [64][260]
    int t = threadIdx.x;
    int base = blockIdx.x * 64;

#pragma unroll
    for (int i = 0; i < 8; i++) {
        int idx = i * 256 + t;
        int row = idx >> 5, col4 = idx & 31;
        int r = base + row; if (r >= N) r = N - 1;
        const float* p = (col4 < 16) ? (g_h_new + (size_t)r * 64 + col4 * 4)
                                     : (hidden  + (size_t)r * 64 + (col4 - 16) * 4);
        float4 v = *(const float4*)p;
        unsigned p0 = f2bf2(v.x, v.y), p1 = f2bf2(v.z, v.w);
        *(uint2*)(As + swz(row, col4 >> 1) + (col4 & 1) * 8) = make_uint2(p0, p1);
    }
#pragma unroll
    for (int i = 0; i < 16; i++) ((uint4*)Bs)[i * 256 + t] = g_Wb_big[i * 256 + t];
    __syncthreads();

    int lane = t & 31, w = t >> 5;
    int mr = (w & 3) * 16;
    int ncb = (w >> 2) * 128;
    int qr = lane >> 2, qc = (lane & 3) * 4;
    float acc[16][4];
#pragma unroll
    for (int n = 0; n < 16; n++)
#pragma unroll
        for (int q = 0; q < 4; q++) acc[n][q] = 0.f;

#pragma unroll
    for (int k0 = 0; k0 < 128; k0 += 16) {
        int c0 = k0 >> 3, c1 = c0 + 1;
        unsigned a0 = *(unsigned*)(As + swz(mr + qr, c0) + qc);
        unsigned a1 = *(unsigned*)(As + swz(mr + qr + 8, c0) + qc);
        unsigned a2 = *(unsigned*)(As + swz(mr + qr, c1) + qc);
        unsigned a3 = *(unsigned*)(As + swz(mr + qr + 8, c1) + qc);
#pragma unroll
        for (int nt = 0; nt < 16; nt++) {
            unsigned b0 = *(unsigned*)(Bs + swz(ncb + nt * 8 + qr, c0) + qc);
            unsigned b1 = *(unsigned*)(Bs + swz(ncb + nt * 8 + qr, c1) + qc);
            mma16816(acc[nt], a0, a1, a2, a3, b0, b1);
        }
    }
    __syncthreads();
#pragma unroll
    for (int nt = 0; nt < 16; nt++) {
        int col = ncb + nt * 8 + (lane & 3) * 2;
        *(float2*)(Gs + (mr + qr) * 260 + col)     = make_float2(acc[nt][0], acc[nt][1]);
        *(float2*)(Gs + (mr + qr + 8) * 260 + col) = make_float2(acc[nt][2], acc[nt][3]);
    }
    __syncthreads();

    int row = t >> 2;                 // 0..63
    int jb = (t & 3) * 16;
    int gr_ = base + row;
    if (gr_ < N) {
#pragma unroll
        for (int jj = 0; jj < 16; jj++) {
            int j = jb + jj;
            float pr = Gs[row * 260 + j]       + b_ih[j]        + b_hh[j];
            float pz = Gs[row * 260 + 64 + j]  + b_ih[64 + j]   + b_hh[64 + j];
            float pi = Gs[row * 260 + 128 + j] + b_ih[128 + j];
            float ph = Gs[row * 260 + 192 + j] + b_hh[128 + j];
            float r = 1.0f / (1.0f + __expf(-pr));
            float z = 1.0f / (1.0f + __expf(-pz));
            float ng = tanhf(fmaf(r, ph, pi));
            float h = hidden[(size_t)gr_ * 64 + j];
            out[(size_t)gr_ * 64 + j] = fmaf(1.0f - z, ng, z * h);
        }
    }
}

// ---------------- launch --------------------------------------------------
extern "C" void kernel_launch(void* const* d_in, const int* in_sizes, int n_in,
                              void* d_out, int out_size) {
    const float* node_feats  = (const float*)d_in[0];
    const float* edge_feats  = (const float*)d_in[1];
    const float* node_hidden = (const float*)d_in[2];
    const int*   src         = (const int*)d_in[3];
    const int*   dst         = (const int*)d_in[4];
    const float* W_edge      = (const float*)d_in[5];
    const float* W_node      = (const float*)d_in[6];
    const float* W_ih        = (const float*)d_in[7];
    const float* W_hh        = (const float*)d_in[8];
    const float* b_ih        = (const float*)d_in[9];
    const float* b_hh        = (const float*)d_in[10];
    float* out = (float*)d_out;

    int E = in_sizes[3];
    int N = in_sizes[2] / HID;

    init_kernel<<<(N * 16 + 255) / 256, 256>>>(node_hidden, N);

    prep_kernel<<<24, 256>>>(W_edge, W_node, W_ih, W_hh);

    nodeproj_kernel<<<(N + 127) / 128, 256>>>(node_feats, N);

    edge_kernel<<<(E + 127) / 128, 256>>>(edge_feats, src, dst, E);

    static const int GRU_SMEM = 16384 + 65536;  // 80 KB dynamic
    cudaFuncSetAttribute(gru_kernel, cudaFuncAttributeMaxDynamicSharedMemorySize, GRU_SMEM);
    gru_kernel<<<(N + 63) / 64, 256, GRU_SMEM>>>(node_hidden, b_ih, b_hh, out, N);
}